// round 8
// baseline (speedup 1.0000x reference)
#include <cuda_runtime.h>
#include <cuda_bf16.h>
#include <math.h>

// Problem constants (fixed by the dataset)
#define NN   50000
#define DD   64
#define EE   800000
#define OUTK 16
#define NF   (NN * DD)          // 3,200,000
#define NF4  (NF / 4)           // 800,000
#define FC_BLOCKS 1024
#define ROWS_PER_BLK 16

// ---------------- device scratch (no allocation allowed) ----------------
// NOTE: never reference these symbols from host code (host shadow != device
// address; on GB300 ATS silently reads host memory). Select via int tags.
__device__ __align__(16) int   g_deg_out[NN];
__device__ __align__(16) int   g_cnt_in[NN];
__device__ __align__(16) int   g_rowptr[NN + 1];
__device__ __align__(16) int   g_fill[NN];
__device__ __align__(16) int   g_csr[EE];
__device__ __align__(16) float g_norm_src[NN];
__device__ __align__(16) float g_norm_dst[NN];
__device__ __align__(16) float g_x[NF];
__device__ __align__(16) float g_y[NF];
__device__ __align__(16) float g_partials[FC_BLOCKS * OUTK];

// ---------------- setup kernels ----------------
__global__ void k_init() {
    int n = blockIdx.x * blockDim.x + threadIdx.x;
    if (n < NN) {
        g_deg_out[n] = 1;   // self loop
        g_cnt_in[n]  = 0;   // self loop accounted as +1 later
    }
}

__global__ void k_degree(const int4* __restrict__ src4, const int4* __restrict__ dst4) {
    int i = blockIdx.x * blockDim.x + threadIdx.x;
    if (i < EE / 4) {
        int4 s = src4[i];
        int4 d = dst4[i];
        atomicAdd(&g_deg_out[s.x], 1); atomicAdd(&g_deg_out[s.y], 1);
        atomicAdd(&g_deg_out[s.z], 1); atomicAdd(&g_deg_out[s.w], 1);
        atomicAdd(&g_cnt_in[d.x], 1);  atomicAdd(&g_cnt_in[d.y], 1);
        atomicAdd(&g_cnt_in[d.z], 1);  atomicAdd(&g_cnt_in[d.w], 1);
    }
}

// single-block parallel scan of cnt_in -> rowptr / fill, plus norms
__global__ void k_scan() {
    __shared__ int warpsum[32];
    const int t    = threadIdx.x;          // 1024 threads
    const int lane = t & 31;
    const int w    = t >> 5;
    const int CH   = (NN + 1023) / 1024;   // 49
    const int base = t * CH;

    int s = 0;
    for (int i = 0; i < CH; i++) {
        int idx = base + i;
        if (idx < NN) s += g_cnt_in[idx];
    }
    // warp inclusive scan
    int v = s;
    #pragma unroll
    for (int off = 1; off < 32; off <<= 1) {
        int u = __shfl_up_sync(0xffffffffu, v, off);
        if (lane >= off) v += u;
    }
    if (lane == 31) warpsum[w] = v;
    __syncthreads();
    if (w == 0) {
        int x = warpsum[lane];
        #pragma unroll
        for (int off = 1; off < 32; off <<= 1) {
            int u = __shfl_up_sync(0xffffffffu, x, off);
            if (lane >= off) x += u;
        }
        warpsum[lane] = x;   // inclusive warp totals
    }
    __syncthreads();
    int run = (v - s) + (w > 0 ? warpsum[w - 1] : 0);   // exclusive prefix

    for (int i = 0; i < CH; i++) {
        int idx = base + i;
        if (idx < NN) {
            int c = g_cnt_in[idx];
            g_rowptr[idx] = run;
            g_fill[idx]   = run;
            run += c;
            g_norm_src[idx] = rsqrtf((float)g_deg_out[idx]);
            g_norm_dst[idx] = rsqrtf((float)(c + 1));
        }
    }
    if (t == 1023) g_rowptr[NN] = run;   // == EE
}

__global__ void k_scatter(const int4* __restrict__ src4, const int4* __restrict__ dst4) {
    int i = blockIdx.x * blockDim.x + threadIdx.x;
    if (i < EE / 4) {
        int4 s = src4[i];
        int4 d = dst4[i];
        g_csr[atomicAdd(&g_fill[d.x], 1)] = s.x;
        g_csr[atomicAdd(&g_fill[d.y], 1)] = s.y;
        g_csr[atomicAdd(&g_fill[d.z], 1)] = s.z;
        g_csr[atomicAdd(&g_fill[d.w], 1)] = s.w;
    }
}

// h0: g_x = F * norm_src  (pre-scaled features; relu(z)*c == relu(z*c), c>0)
__global__ void k_h0(const float4* __restrict__ F4) {
    int i = blockIdx.x * blockDim.x + threadIdx.x;
    if (i < NF4) {
        float s = g_norm_src[i >> 4];     // 16 float4 per node
        float4 v = F4[i];
        v.x *= s; v.y *= s; v.z *= s; v.w *= s;
        ((float4*)g_x)[i] = v;
    }
}

// ---------------- fused GCN layer ----------------
// hin holds h = x*norm_src. Computes:
//   agg[d] = (h[d] + sum_{s in in(d)} h[s]) * norm_dst[d]
//   t      = relu(agg @ W[layer] + b[layer])
//   hout[d]= t * (scale_out ? norm_src[d] : 1)
// inwhich: 0 -> g_x, 1 -> g_y; output goes to the other buffer.
// 512 threads = 16 warps; one warp aggregates one row, then GEMMs it.
__global__ __launch_bounds__(512, 2)
void k_layer(int inwhich, const float* __restrict__ gcn_w,
             const float* __restrict__ gcn_b, int layer, int scale_out) {
    __shared__ float Ws[DD * DD];              // 16 KB
    __shared__ float As[ROWS_PER_BLK * DD];    //  4 KB
    const float* __restrict__ hin  = (inwhich == 0) ? g_x : g_y;
    float*       __restrict__ hout = (inwhich == 0) ? g_y : g_x;
    const int tid  = threadIdx.x;
    const int warp = tid >> 5;
    const int lane = tid & 31;
    const int d    = blockIdx.x * ROWS_PER_BLK + warp;

    // cooperative load of W[layer] (1024 float4 / 512 threads = 2 each)
    const float4* W4 = (const float4*)(gcn_w + layer * DD * DD);
    ((float4*)Ws)[tid]       = W4[tid];
    ((float4*)Ws)[tid + 512] = W4[tid + 512];

    // ---- aggregation: warp per row, lane holds features {2*lane, 2*lane+1} ----
    if (d < NN) {
        const float2* __restrict__ h2 = (const float2*)hin;
        float2 acc = h2[d * 32 + lane];                 // self loop
        const int beg = g_rowptr[d];
        const int end = g_rowptr[d + 1];
        for (int base = beg; base < end; base += 32) {
            const int n = min(32, end - base);
            int idx = (lane < n) ? g_csr[base + lane] : 0;
            for (int j = 0; j < n; j++) {
                int s = __shfl_sync(0xffffffffu, idx, j);
                float2 v = h2[s * 32 + lane];
                acc.x += v.x; acc.y += v.y;
            }
        }
        const float nd = g_norm_dst[d];
        ((float2*)As)[warp * 32 + lane] = make_float2(acc.x * nd, acc.y * nd);
    }
    __syncthreads();

    // ---- GEMM: warp computes its row; lane -> output cols {2*lane, 2*lane+1} ----
    if (d < NN) {
        const float2* Ws2 = (const float2*)Ws;
        float2 b = ((const float2*)(gcn_b + layer * DD))[lane];
        float a0 = b.x, a1 = b.y;
        #pragma unroll
        for (int k = 0; k < DD; k++) {
            float  x = As[warp * DD + k];     // broadcast within warp
            float2 w = Ws2[k * 32 + lane];    // conflict-free LDS.64
            a0 += x * w.x;
            a1 += x * w.y;
        }
        float sc = scale_out ? g_norm_src[d] : 1.0f;
        a0 = fmaxf(a0, 0.f) * sc;
        a1 = fmaxf(a1, 0.f) * sc;
        ((float2*)hout)[d * 32 + lane] = make_float2(a0, a1);
    }
}

// ---------------- final FC: out = fc_w @ flat + fc_b ----------------
// Final activations live in g_y (layer 2 writes g_y when chain starts at g_x).
__global__ void k_fc_partial(const float* __restrict__ fcw) {
    const float4* __restrict__ w4 = (const float4*)fcw;
    const float4* __restrict__ f4 = (const float4*)g_y;

    float acc[OUTK];
    #pragma unroll
    for (int o = 0; o < OUTK; o++) acc[o] = 0.f;

    for (int i = blockIdx.x * blockDim.x + threadIdx.x; i < NF4;
         i += gridDim.x * blockDim.x) {
        float4 f = f4[i];
        #pragma unroll
        for (int o = 0; o < OUTK; o++) {
            float4 w = w4[(size_t)o * NF4 + i];
            acc[o] += w.x * f.x + w.y * f.y + w.z * f.z + w.w * f.w;
        }
    }

    __shared__ float red[256];
    #pragma unroll
    for (int o = 0; o < OUTK; o++) {
        red[threadIdx.x] = acc[o];
        __syncthreads();
        #pragma unroll
        for (int s = 128; s > 0; s >>= 1) {
            if (threadIdx.x < s) red[threadIdx.x] += red[threadIdx.x + s];
            __syncthreads();
        }
        if (threadIdx.x == 0) g_partials[blockIdx.x * OUTK + o] = red[0];
        __syncthreads();
    }
}

__global__ void k_fc_reduce(const float* __restrict__ fcb, float* __restrict__ out) {
    int w = threadIdx.x >> 5;
    int lane = threadIdx.x & 31;
    if (w < OUTK) {
        float s = 0.f;
        for (int b = lane; b < FC_BLOCKS; b += 32)
            s += g_partials[b * OUTK + w];
        #pragma unroll
        for (int off = 16; off > 0; off >>= 1)
            s += __shfl_down_sync(0xffffffffu, s, off);
        if (lane == 0) out[w] = fcb[w] + s;
    }
}

// ---------------- launch ----------------
extern "C" void kernel_launch(void* const* d_in, const int* in_sizes, int n_in,
                              void* d_out, int out_size) {
    const float* F     = (const float*)d_in[0];
    const int*   src   = (const int*)d_in[1];
    const int*   dst   = (const int*)d_in[2];
    const float* gcn_w = (const float*)d_in[3];
    const float* gcn_b = (const float*)d_in[4];
    const float* fc_w  = (const float*)d_in[5];
    const float* fc_b  = (const float*)d_in[6];
    float* out = (float*)d_out;

    // graph build (deterministic work each launch)
    k_init   <<<(NN + 255) / 256, 256>>>();
    k_degree <<<(EE / 4 + 255) / 256, 256>>>((const int4*)src, (const int4*)dst);
    k_scan   <<<1, 1024>>>();
    k_scatter<<<(EE / 4 + 255) / 256, 256>>>((const int4*)src, (const int4*)dst);

    // pre-scale features into g_x
    k_h0<<<(NF4 + 255) / 256, 256>>>((const float4*)F);

    const int LBLK = (NN + ROWS_PER_BLK - 1) / ROWS_PER_BLK;
    // layer 0: g_x -> g_y (output pre-scaled by norm_src)
    k_layer<<<LBLK, 512>>>(0, gcn_w, gcn_b, 0, 1);
    // layer 1: g_y -> g_x (pre-scaled)
    k_layer<<<LBLK, 512>>>(1, gcn_w, gcn_b, 1, 1);
    // layer 2: g_x -> g_y (UNSCALED final activations for FC)
    k_layer<<<LBLK, 512>>>(0, gcn_w, gcn_b, 2, 0);

    // FC head on final activations in g_y (relu already applied)
    k_fc_partial<<<FC_BLOCKS, 256>>>(fc_w);
    k_fc_reduce <<<1, 512>>>(fc_b, out);
}

// round 13
// speedup vs baseline: 1.5275x; 1.5275x over previous
#include <cuda_runtime.h>
#include <cuda_bf16.h>
#include <math.h>

// Problem constants (fixed by the dataset)
#define NN    50000
#define NPAD  50176            // 49 * 1024, vector-friendly padding
#define DD    64
#define EE    800000
#define OUTK  16
#define NF    (NN * DD)        // 3,200,000
#define NF4   (NF / 4)         // 800,000
#define FC_BLOCKS 1024
#define ROWS_PER_BLK 16
#define SCAN_BLKS (NPAD / 1024)   // 49

// ---------------- device scratch (no allocation allowed) ----------------
// NOTE: never reference these symbols from host code (host shadow != device
// address; GB300 ATS silently reads host memory). Select via int tags.
__device__ __align__(16) int   g_deg_out[NPAD];
__device__ __align__(16) int   g_cnt_in[NPAD];
__device__ __align__(16) int   g_rowptr[NPAD + 8];
__device__ __align__(16) int   g_fill[NPAD];
__device__ __align__(16) int   g_csr[EE];
__device__ __align__(16) float g_norm_src[NPAD];
__device__ __align__(16) float g_norm_dst[NPAD];
__device__ __align__(16) float g_x[NF];
__device__ __align__(16) float g_y[NF];
__device__ __align__(16) int   g_blocksum[SCAN_BLKS];
__device__ __align__(16) int   g_blockoff[SCAN_BLKS];
__device__ __align__(16) float g_partials[FC_BLOCKS * OUTK];

// ---------------- setup ----------------
__global__ void k_zero() {                       // zero both counter arrays
    int i = blockIdx.x * blockDim.x + threadIdx.x;
    if (i < NPAD / 4) {
        int4 z = make_int4(0, 0, 0, 0);
        ((int4*)g_cnt_in)[i]  = z;
        ((int4*)g_deg_out)[i] = z;
    }
}

__global__ void k_degree(const int4* __restrict__ src4, const int4* __restrict__ dst4) {
    int i = blockIdx.x * blockDim.x + threadIdx.x;
    if (i < EE / 4) {
        int4 s = src4[i];
        int4 d = dst4[i];
        atomicAdd(&g_deg_out[s.x], 1); atomicAdd(&g_deg_out[s.y], 1);
        atomicAdd(&g_deg_out[s.z], 1); atomicAdd(&g_deg_out[s.w], 1);
        atomicAdd(&g_cnt_in[d.x], 1);  atomicAdd(&g_cnt_in[d.y], 1);
        atomicAdd(&g_cnt_in[d.z], 1);  atomicAdd(&g_cnt_in[d.w], 1);
    }
}

// ---- hierarchical coalesced scan: 49-block reduce -> scan sums -> rescan ----
__global__ void k_scan1() {          // grid 49, block 256: block sums of cnt_in
    __shared__ int wsum[8];
    const int tid = threadIdx.x;
    int4 c = ((const int4*)g_cnt_in)[blockIdx.x * 256 + tid];
    int s = c.x + c.y + c.z + c.w;
    #pragma unroll
    for (int off = 16; off > 0; off >>= 1)
        s += __shfl_down_sync(0xffffffffu, s, off);
    if ((tid & 31) == 0) wsum[tid >> 5] = s;
    __syncthreads();
    if (tid < 8) {
        int v = wsum[tid];
        #pragma unroll
        for (int off = 4; off > 0; off >>= 1)
            v += __shfl_down_sync(0xffu, v, off);
        if (tid == 0) g_blocksum[blockIdx.x] = v;
    }
}

__global__ void k_scan2() {          // 1 block, 64 threads: exclusive scan of 49 sums
    __shared__ int ws[2];
    const int t = threadIdx.x, lane = t & 31, w = t >> 5;
    int s = (t < SCAN_BLKS) ? g_blocksum[t] : 0;
    int v = s;
    #pragma unroll
    for (int off = 1; off < 32; off <<= 1) {
        int u = __shfl_up_sync(0xffffffffu, v, off);
        if (lane >= off) v += u;
    }
    if (lane == 31) ws[w] = v;
    __syncthreads();
    int incl = v + (w == 1 ? ws[0] : 0);
    if (t < SCAN_BLKS) g_blockoff[t] = incl - s;   // exclusive
}

__global__ void k_scan3() {          // grid 49, block 256: rowptr/fill/norms
    __shared__ int wsum[8];
    const int tid  = threadIdx.x;
    const int lane = tid & 31;
    const int w    = tid >> 5;
    const int gi   = blockIdx.x * 256 + tid;       // int4 element index

    int4 c = ((const int4*)g_cnt_in)[gi];
    int tsum = c.x + c.y + c.z + c.w;

    int v = tsum;                                   // warp inclusive scan
    #pragma unroll
    for (int off = 1; off < 32; off <<= 1) {
        int u = __shfl_up_sync(0xffffffffu, v, off);
        if (lane >= off) v += u;
    }
    if (lane == 31) wsum[w] = v;
    __syncthreads();
    int woff = 0;
    if (w > 0) {
        #pragma unroll
        for (int k = 0; k < 7; k++) if (k < w) woff += wsum[k];
    }
    int base = g_blockoff[blockIdx.x] + woff + (v - tsum);

    int4 rp;
    rp.x = base;
    rp.y = base + c.x;
    rp.z = rp.y + c.y;
    rp.w = rp.z + c.z;
    ((int4*)g_rowptr)[gi] = rp;
    ((int4*)g_fill)[gi]   = rp;
    if (gi == NPAD / 4 - 1) g_rowptr[NPAD] = rp.w + c.w;  // defensive (EE)

    int4 dg = ((const int4*)g_deg_out)[gi];
    float4 ns, nd;
    ns.x = rsqrtf((float)(dg.x + 1)); ns.y = rsqrtf((float)(dg.y + 1));
    ns.z = rsqrtf((float)(dg.z + 1)); ns.w = rsqrtf((float)(dg.w + 1));
    nd.x = rsqrtf((float)(c.x + 1));  nd.y = rsqrtf((float)(c.y + 1));
    nd.z = rsqrtf((float)(c.z + 1));  nd.w = rsqrtf((float)(c.w + 1));
    ((float4*)g_norm_src)[gi] = ns;
    ((float4*)g_norm_dst)[gi] = nd;
}

__global__ void k_scatter(const int4* __restrict__ src4, const int4* __restrict__ dst4) {
    int i = blockIdx.x * blockDim.x + threadIdx.x;
    if (i < EE / 4) {
        int4 s = src4[i];
        int4 d = dst4[i];
        g_csr[atomicAdd(&g_fill[d.x], 1)] = s.x;
        g_csr[atomicAdd(&g_fill[d.y], 1)] = s.y;
        g_csr[atomicAdd(&g_fill[d.z], 1)] = s.z;
        g_csr[atomicAdd(&g_fill[d.w], 1)] = s.w;
    }
}

// h0: g_x = F * norm_src  (pre-scaled features; relu(z)*c == relu(z*c), c>0)
__global__ void k_h0(const float4* __restrict__ F4) {
    int i = blockIdx.x * blockDim.x + threadIdx.x;
    if (i < NF4) {
        float s = g_norm_src[i >> 4];     // 16 float4 per node
        float4 v = F4[i];
        v.x *= s; v.y *= s; v.z *= s; v.w *= s;
        ((float4*)g_x)[i] = v;
    }
}

// ---------------- fused GCN layer ----------------
// hin holds h = x*norm_src. Computes:
//   agg[d] = (h[d] + sum_{s in in(d)} h[s]) * norm_dst[d]
//   t      = relu(agg @ W[layer] + b[layer])
//   hout[d]= t * (scale_out ? norm_src[d] : 1)
// inwhich: 0 -> g_x in / g_y out, 1 -> g_y in / g_x out.
__global__ __launch_bounds__(512, 2)
void k_layer(int inwhich, const float* __restrict__ gcn_w,
             const float* __restrict__ gcn_b, int layer, int scale_out) {
    __shared__ float Ws[DD * DD];              // 16 KB
    __shared__ float As[ROWS_PER_BLK * DD];    //  4 KB
    const float* __restrict__ hin  = (inwhich == 0) ? g_x : g_y;
    float*       __restrict__ hout = (inwhich == 0) ? g_y : g_x;
    const int tid  = threadIdx.x;
    const int warp = tid >> 5;
    const int lane = tid & 31;
    const int d    = blockIdx.x * ROWS_PER_BLK + warp;

    // cooperative load of W[layer] (1024 float4 / 512 threads = 2 each)
    const float4* W4 = (const float4*)(gcn_w + layer * DD * DD);
    ((float4*)Ws)[tid]       = W4[tid];
    ((float4*)Ws)[tid + 512] = W4[tid + 512];

    // ---- aggregation: warp per row, lane holds features {2*lane, 2*lane+1} ----
    if (d < NN) {
        const float2* __restrict__ h2 = (const float2*)hin;
        float2 acc = h2[d * 32 + lane];                 // self loop
        const int beg = g_rowptr[d];
        const int end = g_rowptr[d + 1];
        for (int base = beg; base < end; base += 32) {
            const int n = min(32, end - base);
            int idx = (lane < n) ? g_csr[base + lane] : 0;
            // chunks of 8: 8 independent LDGs in flight, predicated accumulate
            for (int j = 0; j < n; j += 8) {
                #pragma unroll
                for (int u = 0; u < 8; u++) {
                    int s = __shfl_sync(0xffffffffu, idx, (j + u) & 31);
                    float2 v = h2[s * 32 + lane];       // s==0 when padded: in-bounds, discarded
                    bool ok = (j + u) < n;
                    acc.x += ok ? v.x : 0.f;
                    acc.y += ok ? v.y : 0.f;
                }
            }
        }
        const float nd = g_norm_dst[d];
        ((float2*)As)[warp * 32 + lane] = make_float2(acc.x * nd, acc.y * nd);
    }
    __syncthreads();

    // ---- GEMM: warp computes its row; lane -> output cols {2*lane, 2*lane+1} ----
    if (d < NN) {
        const float2* Ws2 = (const float2*)Ws;
        float2 b = ((const float2*)(gcn_b + layer * DD))[lane];
        float a0 = b.x, a1 = b.y;
        #pragma unroll
        for (int k = 0; k < DD; k++) {
            float  x = As[warp * DD + k];     // broadcast within warp
            float2 w = Ws2[k * 32 + lane];    // conflict-free LDS.64
            a0 += x * w.x;
            a1 += x * w.y;
        }
        float sc = scale_out ? g_norm_src[d] : 1.0f;
        a0 = fmaxf(a0, 0.f) * sc;
        a1 = fmaxf(a1, 0.f) * sc;
        ((float2*)hout)[d * 32 + lane] = make_float2(a0, a1);
    }
}

// ---------------- final FC: out = fc_w @ flat + fc_b ----------------
// Final activations live in g_y (layer 2 writes g_y).
__global__ void k_fc_partial(const float* __restrict__ fcw) {
    const float4* __restrict__ w4 = (const float4*)fcw;
    const float4* __restrict__ f4 = (const float4*)g_y;

    float acc[OUTK];
    #pragma unroll
    for (int o = 0; o < OUTK; o++) acc[o] = 0.f;

    for (int i = blockIdx.x * blockDim.x + threadIdx.x; i < NF4;
         i += gridDim.x * blockDim.x) {
        float4 f = f4[i];
        #pragma unroll
        for (int o = 0; o < OUTK; o++) {
            float4 w = w4[(size_t)o * NF4 + i];
            acc[o] += w.x * f.x + w.y * f.y + w.z * f.z + w.w * f.w;
        }
    }

    __shared__ float red[256];
    #pragma unroll
    for (int o = 0; o < OUTK; o++) {
        red[threadIdx.x] = acc[o];
        __syncthreads();
        #pragma unroll
        for (int s = 128; s > 0; s >>= 1) {
            if (threadIdx.x < s) red[threadIdx.x] += red[threadIdx.x + s];
            __syncthreads();
        }
        if (threadIdx.x == 0) g_partials[blockIdx.x * OUTK + o] = red[0];
        __syncthreads();
    }
}

__global__ void k_fc_reduce(const float* __restrict__ fcb, float* __restrict__ out) {
    int w = threadIdx.x >> 5;
    int lane = threadIdx.x & 31;
    if (w < OUTK) {
        float s = 0.f;
        for (int b = lane; b < FC_BLOCKS; b += 32)
            s += g_partials[b * OUTK + w];
        #pragma unroll
        for (int off = 16; off > 0; off >>= 1)
            s += __shfl_down_sync(0xffffffffu, s, off);
        if (lane == 0) out[w] = fcb[w] + s;
    }
}

// ---------------- launch ----------------
extern "C" void kernel_launch(void* const* d_in, const int* in_sizes, int n_in,
                              void* d_out, int out_size) {
    const float* F     = (const float*)d_in[0];
    const int*   src   = (const int*)d_in[1];
    const int*   dst   = (const int*)d_in[2];
    const float* gcn_w = (const float*)d_in[3];
    const float* gcn_b = (const float*)d_in[4];
    const float* fc_w  = (const float*)d_in[5];
    const float* fc_b  = (const float*)d_in[6];
    float* out = (float*)d_out;

    // graph build (deterministic work each launch)
    k_zero   <<<(NPAD / 4 + 255) / 256, 256>>>();
    k_degree <<<(EE / 4 + 255) / 256, 256>>>((const int4*)src, (const int4*)dst);
    k_scan1  <<<SCAN_BLKS, 256>>>();
    k_scan2  <<<1, 64>>>();
    k_scan3  <<<SCAN_BLKS, 256>>>();
    k_scatter<<<(EE / 4 + 255) / 256, 256>>>((const int4*)src, (const int4*)dst);

    // pre-scale features into g_x
    k_h0<<<(NF4 + 255) / 256, 256>>>((const float4*)F);

    const int LBLK = (NN + ROWS_PER_BLK - 1) / ROWS_PER_BLK;
    // layer 0: g_x -> g_y (output pre-scaled by norm_src)
    k_layer<<<LBLK, 512>>>(0, gcn_w, gcn_b, 0, 1);
    // layer 1: g_y -> g_x (pre-scaled)
    k_layer<<<LBLK, 512>>>(1, gcn_w, gcn_b, 1, 1);
    // layer 2: g_x -> g_y (UNSCALED final activations for FC)
    k_layer<<<LBLK, 512>>>(0, gcn_w, gcn_b, 2, 0);

    // FC head on final activations in g_y (relu already applied)
    k_fc_partial<<<FC_BLOCKS, 256>>>(fc_w);
    k_fc_reduce <<<1, 512>>>(fc_b, out);
}